// round 11
// baseline (speedup 1.0000x reference)
#include <cuda_runtime.h>
#include <cuda_fp16.h>
#include <math.h>

#define NN 50000
#define NE 800000
#define GSTRIDE 68          // A smem stride (conflict-free frag loads)
#define AGGQ 8              // edges per half-warp window
#define GRID 296            // < 2 x 152 SMs -> all blocks co-resident
#define TPB 256
#define GRIDT (GRID * TPB)  // 75776
#define SCAN_TILES 196      // ceil(50000/256)

// ---------------- scratch (static __device__, allocation-free) ----------------
__device__ uint4  g_projh[NN * 16];     // [N][16] x 16B: {b0 4h | b1 4h} per sub
__device__ float4 g_h1a[NN * 16];       // layer-1 hidden fp32
__device__ float4 g_h2a[NN * 16];       // layer-2 hidden fp32
__device__ int    g_deg[NN];            // self-cleared by scan each run
__device__ int    g_cursor[NN];
__device__ int    g_tflag[256];
__device__ int2   g_csr[NE];            // {src | etype<<17, dst}
__device__ uint2  g_wpack[2 * 24 * 8 * 32];   // frag-major tf32 weights
__device__ float  g_facc;
__device__ float  g_sink;
__device__ int            g_bar_count;
__device__ volatile int   g_bar_sense;

static __device__ __forceinline__ unsigned f2tf32(float f)
{
    unsigned u;
    asm("cvt.rna.tf32.f32 %0, %1;" : "=r"(u) : "f"(f));
    return u;
}

// Replay-safe grid barrier: sense read at kernel entry, count self-resets.
static __device__ __forceinline__ void gbar(int& sense)
{
    __syncthreads();
    if (threadIdx.x == 0) {
        __threadfence();
        if (atomicAdd(&g_bar_count, 1) == GRID - 1) {
            g_bar_count = 0;
            __threadfence();
            g_bar_sense = sense ^ 1;
        } else {
            while (g_bar_sense == sense) { }
        }
    }
    __syncthreads();
    sense ^= 1;
}

// ---------------- tf32 tensor-core tile: 64 nodes x [V0|V1|loop_w] ----------------
static __device__ __forceinline__ void gemm_tile(
    unsigned* xs, int tileIdx, const float* __restrict__ x,
    const uint2* __restrict__ wpackL, const float* __restrict__ biasL,
    int relu_in, __half* __restrict__ projh, float* __restrict__ h)
{
    const int tid = threadIdx.x;
    const int nbase = tileIdx * 64;

    {   // stage A as tf32 (L2-only loads: x may be h1 modified by RED at L2)
        int nl = tid >> 2;
        int c0 = (tid & 3) * 16;
        int n = nbase + nl;
        const float4* xr = (const float4*)(x + (size_t)n * 64 + c0);
#pragma unroll
        for (int u = 0; u < 4; ++u) {
            float4 v = (n < NN) ? __ldcg(xr + u) : make_float4(0.f, 0.f, 0.f, 0.f);
            if (relu_in) {
                v.x = fmaxf(v.x, 0.f); v.y = fmaxf(v.y, 0.f);
                v.z = fmaxf(v.z, 0.f); v.w = fmaxf(v.w, 0.f);
            }
            unsigned* dstp = xs + nl * GSTRIDE + c0 + u * 4;
            dstp[0] = f2tf32(v.x); dstp[1] = f2tf32(v.y);
            dstp[2] = f2tf32(v.z); dstp[3] = f2tf32(v.w);
        }
    }
    __syncthreads();

    const int w    = tid >> 5;
    const int lane = tid & 31;
    const int m0   = (w & 3) << 4;
    const int ng   = w >> 2;
    const int g    = lane >> 2;
    const int t4   = lane & 3;

    float acc[12][4];
#pragma unroll
    for (int j = 0; j < 12; ++j)
#pragma unroll
        for (int c = 0; c < 4; ++c) acc[j][c] = 0.f;

    const uint2* wp = wpackL + ((size_t)ng * 3072) + lane;

#pragma unroll
    for (int s = 0; s < 8; ++s) {
        int k0 = s * 8;
        unsigned a0 = xs[(m0 + g) * GSTRIDE + k0 + t4];
        unsigned a1 = xs[(m0 + g + 8) * GSTRIDE + k0 + t4];
        unsigned a2 = xs[(m0 + g) * GSTRIDE + k0 + t4 + 4];
        unsigned a3 = xs[(m0 + g + 8) * GSTRIDE + k0 + t4 + 4];
        uint2 b[12];
#pragma unroll
        for (int j = 0; j < 12; ++j) b[j] = __ldg(wp + (j * 8 + s) * 32);
#pragma unroll
        for (int j = 0; j < 12; ++j)
            asm volatile(
                "mma.sync.aligned.m16n8k8.row.col.f32.tf32.tf32.f32 "
                "{%0,%1,%2,%3}, {%4,%5,%6,%7}, {%8,%9}, {%0,%1,%2,%3};"
                : "+f"(acc[j][0]), "+f"(acc[j][1]), "+f"(acc[j][2]), "+f"(acc[j][3])
                : "r"(a0), "r"(a1), "r"(a2), "r"(a3), "r"(b[j].x), "r"(b[j].y));
    }

    const int row0 = nbase + m0 + g;
#pragma unroll
    for (int j = 0; j < 12; ++j) {
        int o = ng * 96 + j * 8 + t4 * 2;
#pragma unroll
        for (int rr = 0; rr < 2; ++rr) {
            int n = row0 + rr * 8;
            if (n >= NN) continue;
            float v0 = acc[j][rr * 2], v1 = acc[j][rr * 2 + 1];
            if (o < 128) {
                int basis = o >> 6, c64 = o & 63;
                int off = ((c64 >> 2) << 3) + (basis << 2) + (c64 & 3);
                *(__half2*)((__half*)projh + (size_t)n * 128 + off) =
                    __floats2half2_rn(v0, v1);
            } else {
                int c = o - 128;
                float2 f;
                f.x = v0 + __ldg(biasL + c);
                f.y = v1 + __ldg(biasL + c + 1);
                *(float2*)(h + (size_t)n * 64 + c) = f;
            }
        }
    }
    __syncthreads();   // protect xs before next tile restages
}

// ---------------- edge-balanced aggregation phase ----------------
static __device__ __forceinline__ void agg_phase(
    const uint4* __restrict__ proj, const float* scomp, float4* __restrict__ h)
{
    const int slot = (blockIdx.x * TPB + threadIdx.x) >> 4;
    const int sub = threadIdx.x & 15;
    const unsigned hmask = 0xFFFFu << (threadIdx.x & 16);

    for (int q = slot; q < NE / AGGQ; q += GRIDT >> 4) {
        int j0 = q * AGGQ;
        int2 rec = (sub < AGGQ) ? __ldg(g_csr + j0 + sub) : make_int2(0, 0);

        int pk[AGGQ], dk[AGGQ];
#pragma unroll
        for (int k = 0; k < AGGQ; ++k) {
            pk[k] = __shfl_sync(hmask, rec.x, k, 16);
            dk[k] = __shfl_sync(hmask, rec.y, k, 16);
        }
        uint4 a[AGGQ];
#pragma unroll
        for (int k = 0; k < AGGQ; ++k)
            a[k] = __ldcg(proj + (size_t)(pk[k] & 0x1FFFF) * 16 + sub);

        float4 acc = make_float4(0.f, 0.f, 0.f, 0.f);
        int cur_d = dk[0];

#define FLUSH()                                                             \
        {                                                                   \
            float4* hp = h + (size_t)cur_d * 16 + sub;                      \
            asm volatile("red.global.add.v4.f32 [%0], {%1,%2,%3,%4};"       \
                         :: "l"(hp), "f"(acc.x), "f"(acc.y), "f"(acc.z),    \
                            "f"(acc.w) : "memory");                         \
        }
#pragma unroll
        for (int k = 0; k < AGGQ; ++k) {
            if (dk[k] != cur_d) {
                FLUSH();
                acc = make_float4(0.f, 0.f, 0.f, 0.f);
                cur_d = dk[k];
            }
            int tt = pk[k] >> 17;
            float c0 = scomp[2 * tt], c1 = scomp[2 * tt + 1];
            float2 f0a = __half22float2(*(__half2*)&a[k].x);
            float2 f0b = __half22float2(*(__half2*)&a[k].y);
            float2 f1a = __half22float2(*(__half2*)&a[k].z);
            float2 f1b = __half22float2(*(__half2*)&a[k].w);
            acc.x = fmaf(c0, f0a.x, fmaf(c1, f1a.x, acc.x));
            acc.y = fmaf(c0, f0a.y, fmaf(c1, f1a.y, acc.y));
            acc.z = fmaf(c0, f0b.x, fmaf(c1, f1b.x, acc.z));
            acc.w = fmaf(c0, f0b.y, fmaf(c1, f1b.y, acc.w));
        }
        FLUSH();
#undef FLUSH
    }
}

// ---------------------------------------------------------------------------
// Persistent mega-kernel: all phases, grid-wide barriers, one launch.
// ---------------------------------------------------------------------------
__global__ void __launch_bounds__(TPB, 2) mega_kernel(
    const float* __restrict__ features, const float* __restrict__ V,
    const float* __restrict__ comp, const float* __restrict__ lw,
    const float* __restrict__ bias, const float* __restrict__ fcw,
    const float* __restrict__ fc_b, const int* __restrict__ src,
    const int* __restrict__ dst, const int* __restrict__ et,
    float* __restrict__ out)
{
    __shared__ unsigned xs[64 * GSTRIDE];   // 17408 B
    __shared__ float red[TPB];
    __shared__ float scomp[16];
    __shared__ int wsum[8], wpre[8];
    __shared__ int s_prefix;

    const int tid = threadIdx.x;
    const int bid = blockIdx.x;
    const int gid = bid * TPB + tid;
    int sense = g_bar_sense;                // entry-read: replay-safe

    // ================= P0: resets + wprep + hist + fc_w warm =================
    if (gid < 256) g_tflag[gid] = 0;
    if (gid == 0) atomicExch((int*)&g_facc, 0);   // fp 0.0 bit pattern

    for (int id = gid; id < 12288; id += GRIDT) {
        int lay  = id / 6144;
        int r    = id - lay * 6144;
        int nt   = r >> 8;
        int s    = (r >> 5) & 7;
        int ln   = r & 31;
        int o  = nt * 8 + (ln >> 2);
        int k0 = s * 8 + (ln & 3);
        float w0, w1;
        if (o < 128) {
            int b = o >> 6, c = o & 63;
            w0 = V[(((lay * 2 + b) * 64) + k0) * 64 + c];
            w1 = V[(((lay * 2 + b) * 64) + k0 + 4) * 64 + c];
        } else {
            w0 = lw[(lay * 64 + k0) * 64 + (o - 128)];
            w1 = lw[(lay * 64 + k0 + 4) * 64 + (o - 128)];
        }
        g_wpack[id] = make_uint2(f2tf32(w0), f2tf32(w1));
    }
    {   // degree histogram (deg zeroed by previous run's scan / module init)
        const int4* dst4 = (const int4*)dst;
        for (int t = gid; t < NE / 4; t += GRIDT) {
            int4 d = __ldg(dst4 + t);
            atomicAdd(&g_deg[d.x], 1);
            atomicAdd(&g_deg[d.y], 1);
            atomicAdd(&g_deg[d.z], 1);
            atomicAdd(&g_deg[d.w], 1);
        }
    }
    {   // warm fc_w into L2/L1 (read-only)
        const float4* w4 = (const float4*)fcw;
        float s = 0.f;
        for (int i = gid; i < NN * 16; i += GRIDT) {
            float4 v = __ldg(w4 + i);
            s += v.x + v.y + v.z + v.w;
        }
        if (s == 1.2345e37f) g_sink = s;
    }
    gbar(sense);

    // ================= P1: decoupled-lookback scan (196 tiles, self-clear deg)
    for (int tile = bid; tile < SCAN_TILES; tile += GRID) {
        const int warp = tid >> 5, lane = tid & 31;
        const int g = tile * 256 + tid;
        int v = (g < NN) ? g_deg[g] : 0;
        int x = v;
#pragma unroll
        for (int d = 1; d < 32; d <<= 1) {
            int y = __shfl_up_sync(0xFFFFFFFFu, x, d);
            if (lane >= d) x += y;
        }
        if (lane == 31) wsum[warp] = x;
        if (tid == 32) s_prefix = 0;
        __syncthreads();
        if (warp == 0 && lane < 8) {
            int sv = wsum[lane];
            int p = sv;
#pragma unroll
            for (int d = 1; d < 8; d <<= 1) {
                int y = __shfl_up_sync(0xFFu, p, d);
                if (lane >= d) p += y;
            }
            wpre[lane] = p - sv;
            if (lane == 7) atomicExch(&g_tflag[tile], p + 1);
        }
        if (tile > 0 && warp == 1) {
            int sum = 0;
            for (int base = tile - 1; base >= 0; base -= 32) {
                int idx = base - lane;
                int val = 0;
                if (idx >= 0) {
                    int f;
                    do { f = atomicAdd(&g_tflag[idx], 0); } while (f == 0);
                    val = f - 1;
                }
#pragma unroll
                for (int o = 16; o; o >>= 1)
                    val += __shfl_xor_sync(0xFFFFFFFFu, val, o);
                sum += val;
            }
            if (lane == 0) s_prefix = sum;
        }
        __syncthreads();
        if (g < NN) {
            g_cursor[g] = s_prefix + wpre[warp] + x - v;
            g_deg[g] = 0;                     // ready for next replay
        }
    }
    gbar(sense);

    // ================= P2: gemm0 + scatter, interleaved work units ==========
    for (int u = bid; u < 782 + 782; u += GRID) {
        if (u < 782) {
            gemm_tile(xs, u, features, g_wpack, bias, 0,
                      (__half*)g_projh, (float*)g_h1a);
        } else {
            int base = (u - 782) * 1024;
#pragma unroll
            for (int k = 0; k < 4; ++k) {
                int e = base + tid + k * 256;
                if (e < NE) {
                    int d = __ldg(dst + e);
                    int pos = atomicAdd(&g_cursor[d], 1);
                    g_csr[pos] = make_int2(__ldg(src + e) | (__ldg(et + e) << 17), d);
                }
            }
        }
    }
    gbar(sense);

    // ================= P3: agg layer 0 ======================================
    if (tid < 16) scomp[tid] = comp[tid];
    __syncthreads();
    agg_phase(g_projh, scomp, g_h1a);
    gbar(sense);

    // ================= P4: gemm1 (reads h1 via L2, relu) ====================
    for (int u = bid; u < 782; u += GRID)
        gemm_tile(xs, u, (const float*)g_h1a, g_wpack + 6144, bias + 64, 1,
                  (__half*)g_projh, (float*)g_h2a);
    gbar(sense);

    // ================= P5: agg layer 1 ======================================
    __syncthreads();
    if (tid < 16) scomp[tid] = comp[16 + tid];
    __syncthreads();
    agg_phase(g_projh, scomp, g_h2a);
    gbar(sense);

    // ================= P6: FC readout =======================================
    {
        const float4* a4 = (const float4*)g_h2a;
        const float4* w4 = (const float4*)fcw;
        float s = 0.f;
        for (int i = gid; i < NN * 16; i += GRIDT) {
            float4 xa = __ldcg(a4 + i);       // h2 modified by RED at L2
            float4 xw = __ldg(w4 + i);
            s += xa.x * xw.x + xa.y * xw.y + xa.z * xw.z + xa.w * xw.w;
        }
        red[tid] = s;
        __syncthreads();
        for (int st = 128; st > 0; st >>= 1) {
            if (tid < st) red[tid] += red[tid + st];
            __syncthreads();
        }
        if (tid == 0) atomicAdd(&g_facc, red[0]);
    }
    gbar(sense);

    if (gid == 0) {
        float tot = atomicAdd(&g_facc, 0.f);
        out[0] = 1.f / (1.f + expf(-(tot + fc_b[0])));
    }
}

// ---------------------------------------------------------------------------
extern "C" void kernel_launch(void* const* d_in, const int* in_sizes, int n_in,
                              void* d_out, int out_size)
{
    const float* features = (const float*)d_in[0];
    const float* V        = (const float*)d_in[1];
    const float* comp     = (const float*)d_in[2];
    const float* loop_w   = (const float*)d_in[3];
    const float* bias     = (const float*)d_in[4];
    const float* fc_w     = (const float*)d_in[5];
    const float* fc_b     = (const float*)d_in[6];
    const int*   src      = (const int*)d_in[7];
    const int*   dst      = (const int*)d_in[8];
    const int*   et       = (const int*)d_in[9];
    float* out = (float*)d_out;

    mega_kernel<<<GRID, TPB>>>(features, V, comp, loop_w, bias, fc_w, fc_b,
                               src, dst, et, out);
}

// round 12
// speedup vs baseline: 1.1034x; 1.1034x over previous
#include <cuda_runtime.h>
#include <cuda_fp16.h>
#include <math.h>

#define NN 50000
#define NE 800000
#define NTILES 98      // ceil((NN+1)/512)
#define GSTRIDE 68     // A smem stride (conflict-free frag loads)
#define AGGQ 8         // edges per half-warp quota

// ---------------- scratch (static __device__, allocation-free) ----------------
__device__ uint4  g_projh[NN * 16];     // [N][16] x 16B: {b0 4h | b1 4h} per sub
__device__ float4 g_h1a[NN * 16];       // layer-1 hidden fp32
__device__ float4 g_h2a[NN * 16];       // layer-2 hidden fp32
__device__ int    g_deg[NN];            // self-clearing (scan zeroes after read)
__device__ int    g_cursor[NN];
__device__ int    g_tflag[128];         // cleared by scatter each run
__device__ int2   g_csr[NE];            // {src | etype<<17, dst}
__device__ uint2  g_wpack[2 * 24 * 8 * 32];   // frag-major tf32 weights
__device__ float  g_facc;
__device__ int    g_fcnt;
__device__ float  g_sink;

static __device__ __forceinline__ unsigned f2tf32(float f)
{
    unsigned u;
    asm("cvt.rna.tf32.f32 %0, %1;" : "=r"(u) : "f"(f));
    return u;
}

// ---------------- CSR build (side stream) ----------------
__global__ void __launch_bounds__(256) hist_kernel(const int4* __restrict__ dst4,
                                                   int* __restrict__ deg)
{
    int t = blockIdx.x * 256 + threadIdx.x;
    if (t >= NE / 4) return;
    int4 d = __ldg(dst4 + t);
    atomicAdd(&deg[d.x], 1);
    atomicAdd(&deg[d.y], 1);
    atomicAdd(&deg[d.z], 1);
    atomicAdd(&deg[d.w], 1);
}

// Warp-shuffle decoupled-lookback scan; self-clears deg for the next replay.
__global__ void __launch_bounds__(512) scan_kernel(
    int* __restrict__ deg, int* __restrict__ cursor, int* __restrict__ tflag)
{
    __shared__ int wsum[16];
    __shared__ int wpre[16];
    __shared__ int s_prefix;
    const int t = threadIdx.x;
    const int warp = t >> 5;
    const int lane = t & 31;
    const int tile = blockIdx.x;
    const int g = tile * 512 + t;

    int v = (g < NN) ? deg[g] : 0;
    int x = v;
#pragma unroll
    for (int d = 1; d < 32; d <<= 1) {
        int y = __shfl_up_sync(0xFFFFFFFFu, x, d);
        if (lane >= d) x += y;
    }
    if (lane == 31) wsum[warp] = x;
    if (t == 32) s_prefix = 0;       // warp1 lane0 (overwritten by lookback)
    __syncthreads();

    // warp 0: scan the 16 warp sums, publish tile aggregate
    if (warp == 0 && lane < 16) {
        int s = wsum[lane];
        int p = s;
#pragma unroll
        for (int d = 1; d < 16; d <<= 1) {
            int y = __shfl_up_sync(0xFFFFu, p, d);
            if (lane >= d) p += y;
        }
        wpre[lane] = p - s;          // exclusive warp prefix
        if (lane == 15) atomicExch(&tflag[tile], p + 1);
    }

    // warp 1: lookback over predecessor tiles (concurrent with warp 0)
    if (tile > 0 && warp == 1) {
        int sum = 0;
        for (int base = tile - 1; base >= 0; base -= 32) {
            int idx = base - lane;
            int val = 0;
            if (idx >= 0) {
                int f;
                do { f = atomicAdd(&tflag[idx], 0); } while (f == 0);
                val = f - 1;
            }
#pragma unroll
            for (int o = 16; o; o >>= 1) val += __shfl_xor_sync(0xFFFFFFFFu, val, o);
            sum += val;
        }
        if (lane == 0) s_prefix = sum;
    }
    __syncthreads();

    if (g < NN) {
        cursor[g] = s_prefix + wpre[warp] + x - v;   // exclusive prefix
        deg[g] = 0;                                  // ready for next replay
    }
}

// 1 edge/thread; block 0 clears tflag (safe: stream-ordered after scan).
__global__ void __launch_bounds__(256) scatter_kernel(
    const int* __restrict__ src, const int* __restrict__ dst,
    const int* __restrict__ et, int* __restrict__ cursor,
    int2* __restrict__ csr, int* __restrict__ tflag)
{
    if (blockIdx.x == 0 && threadIdx.x < 128) tflag[threadIdx.x] = 0;
    int e = blockIdx.x * 256 + threadIdx.x;
    if (e >= NE) return;
    int d = __ldg(dst + e);
    int pos = atomicAdd(&cursor[d], 1);
    csr[pos] = make_int2(__ldg(src + e) | (__ldg(et + e) << 17), d);
}

// L2 warmer for fc_w (idle side stream; joined before fc_kernel)
__global__ void __launch_bounds__(256) prefetch_kernel(const float4* __restrict__ w)
{
    int tid = blockIdx.x * 256 + threadIdx.x;
    float s = 0.f;
    for (int i = tid; i < NN * 16; i += 256 * 256) {
        float4 v = __ldg(w + i);
        s += v.x + v.y + v.z + v.w;
    }
    if (s == 1.2345e37f) g_sink = s;   // never taken; defeats DCE
}

// ---------------------------------------------------------------------------
// Weight prep + FC accumulator reset
// ---------------------------------------------------------------------------
__global__ void __launch_bounds__(256) wprep_kernel(
    const float* __restrict__ V, const float* __restrict__ lw,
    uint2* __restrict__ wpack)
{
    int id = blockIdx.x * 256 + threadIdx.x;
    if (id == 0) { g_facc = 0.f; g_fcnt = 0; }
    if (id >= 2 * 24 * 8 * 32) return;
    int lay  = id / 6144;
    int r    = id - lay * 6144;
    int nt   = r >> 8;
    int s    = (r >> 5) & 7;
    int lane = r & 31;
    int o  = nt * 8 + (lane >> 2);
    int k0 = s * 8 + (lane & 3);
    float w0, w1;
    if (o < 128) {
        int b = o >> 6, c = o & 63;
        w0 = V[(((lay * 2 + b) * 64) + k0) * 64 + c];
        w1 = V[(((lay * 2 + b) * 64) + k0 + 4) * 64 + c];
    } else {
        w0 = lw[(lay * 64 + k0) * 64 + (o - 128)];
        w1 = lw[(lay * 64 + k0 + 4) * 64 + (o - 128)];
    }
    wpack[id] = make_uint2(f2tf32(w0), f2tf32(w1));
}

// ---------------------------------------------------------------------------
// Tensor-core node GEMM: [50000x64] @ [64x192] via mma.sync.m16n8k8.tf32.
// ---------------------------------------------------------------------------
__global__ void __launch_bounds__(256) gemm_tc(
    const float* __restrict__ x, const uint2* __restrict__ wpack,
    const float* __restrict__ bias, __half* __restrict__ projh,
    float* __restrict__ h, int relu_in)
{
    __shared__ unsigned xs[64 * GSTRIDE];
    const int tid = threadIdx.x;
    const int nbase = blockIdx.x * 64;

    {
        int nl = tid >> 2;
        int c0 = (tid & 3) * 16;
        int n = nbase + nl;
        const float4* xr = (const float4*)(x + (size_t)n * 64 + c0);
#pragma unroll
        for (int u = 0; u < 4; ++u) {
            float4 v = (n < NN) ? __ldg(xr + u) : make_float4(0.f, 0.f, 0.f, 0.f);
            if (relu_in) {
                v.x = fmaxf(v.x, 0.f); v.y = fmaxf(v.y, 0.f);
                v.z = fmaxf(v.z, 0.f); v.w = fmaxf(v.w, 0.f);
            }
            unsigned* dst = xs + nl * GSTRIDE + c0 + u * 4;
            dst[0] = f2tf32(v.x); dst[1] = f2tf32(v.y);
            dst[2] = f2tf32(v.z); dst[3] = f2tf32(v.w);
        }
    }
    __syncthreads();

    const int w    = tid >> 5;
    const int lane = tid & 31;
    const int m0   = (w & 3) << 4;
    const int ng   = w >> 2;
    const int g    = lane >> 2;
    const int t4   = lane & 3;

    float acc[12][4];
#pragma unroll
    for (int j = 0; j < 12; ++j)
#pragma unroll
        for (int c = 0; c < 4; ++c) acc[j][c] = 0.f;

    const uint2* wp = wpack + ((size_t)ng * 12 * 8 * 32) + lane;

#pragma unroll
    for (int s = 0; s < 8; ++s) {
        int k0 = s * 8;
        unsigned a0 = xs[(m0 + g) * GSTRIDE + k0 + t4];
        unsigned a1 = xs[(m0 + g + 8) * GSTRIDE + k0 + t4];
        unsigned a2 = xs[(m0 + g) * GSTRIDE + k0 + t4 + 4];
        unsigned a3 = xs[(m0 + g + 8) * GSTRIDE + k0 + t4 + 4];
        uint2 b[12];
#pragma unroll
        for (int j = 0; j < 12; ++j) b[j] = __ldg(wp + (j * 8 + s) * 32);
#pragma unroll
        for (int j = 0; j < 12; ++j)
            asm volatile(
                "mma.sync.aligned.m16n8k8.row.col.f32.tf32.tf32.f32 "
                "{%0,%1,%2,%3}, {%4,%5,%6,%7}, {%8,%9}, {%0,%1,%2,%3};"
                : "+f"(acc[j][0]), "+f"(acc[j][1]), "+f"(acc[j][2]), "+f"(acc[j][3])
                : "r"(a0), "r"(a1), "r"(a2), "r"(a3), "r"(b[j].x), "r"(b[j].y));
    }

    const int row0 = nbase + m0 + g;
#pragma unroll
    for (int j = 0; j < 12; ++j) {
        int o = ng * 96 + j * 8 + t4 * 2;
#pragma unroll
        for (int rr = 0; rr < 2; ++rr) {
            int n = row0 + rr * 8;
            if (n >= NN) continue;
            float v0 = acc[j][rr * 2], v1 = acc[j][rr * 2 + 1];
            if (o < 128) {
                int basis = o >> 6, c64 = o & 63;
                int off = ((c64 >> 2) << 3) + (basis << 2) + (c64 & 3);
                *(__half2*)((__half*)projh + (size_t)n * 128 + off) =
                    __floats2half2_rn(v0, v1);
            } else {
                int c = o - 128;
                float2 f;
                f.x = v0 + __ldg(bias + c);
                f.y = v1 + __ldg(bias + c + 1);
                *(float2*)(h + (size_t)n * 64 + c) = f;
            }
        }
    }
}

// ---------------------------------------------------------------------------
// Edge-balanced aggregation: half-warp per 8-edge CSR window.
// ---------------------------------------------------------------------------
__global__ void __launch_bounds__(256) agg_kernel(
    const uint4* __restrict__ proj, const int2* __restrict__ csr,
    const float* __restrict__ comp_l, float4* __restrict__ h)
{
    __shared__ float scomp[16];
    if (threadIdx.x < 16) scomp[threadIdx.x] = comp_l[threadIdx.x];
    __syncthreads();

    int gid = blockIdx.x * 256 + threadIdx.x;
    int q = gid >> 4;
    if (q >= NE / AGGQ) return;
    int sub = gid & 15;
    int j0 = q * AGGQ;
    unsigned hmask = 0xFFFFu << (threadIdx.x & 16);

    int2 rec = (sub < AGGQ) ? __ldg(csr + j0 + sub) : make_int2(0, 0);

    int pk[AGGQ], dk[AGGQ];
#pragma unroll
    for (int k = 0; k < AGGQ; ++k) {
        pk[k] = __shfl_sync(hmask, rec.x, k, 16);
        dk[k] = __shfl_sync(hmask, rec.y, k, 16);
    }

    uint4 a[AGGQ];
#pragma unroll
    for (int k = 0; k < AGGQ; ++k)
        a[k] = __ldg(proj + (size_t)(pk[k] & 0x1FFFF) * 16 + sub);

    float4 acc = make_float4(0.f, 0.f, 0.f, 0.f);
    int cur_d = dk[0];

#define FLUSH()                                                             \
    {                                                                       \
        float4* hp = h + (size_t)cur_d * 16 + sub;                          \
        asm volatile("red.global.add.v4.f32 [%0], {%1,%2,%3,%4};"           \
                     :: "l"(hp), "f"(acc.x), "f"(acc.y), "f"(acc.z),        \
                        "f"(acc.w) : "memory");                             \
    }

#pragma unroll
    for (int k = 0; k < AGGQ; ++k) {
        if (dk[k] != cur_d) {
            FLUSH();
            acc = make_float4(0.f, 0.f, 0.f, 0.f);
            cur_d = dk[k];
        }
        int tt = pk[k] >> 17;
        float c0 = scomp[2 * tt], c1 = scomp[2 * tt + 1];
        float2 f0a = __half22float2(*(__half2*)&a[k].x);
        float2 f0b = __half22float2(*(__half2*)&a[k].y);
        float2 f1a = __half22float2(*(__half2*)&a[k].z);
        float2 f1b = __half22float2(*(__half2*)&a[k].w);
        acc.x = fmaf(c0, f0a.x, fmaf(c1, f1a.x, acc.x));
        acc.y = fmaf(c0, f0a.y, fmaf(c1, f1a.y, acc.y));
        acc.z = fmaf(c0, f0b.x, fmaf(c1, f1b.x, acc.z));
        acc.w = fmaf(c0, f0b.y, fmaf(c1, f1b.y, acc.w));
    }
    FLUSH();
#undef FLUSH
}

// ---------------------------------------------------------------------------
// FC readout: single kernel; last block applies sigmoid.
// ---------------------------------------------------------------------------
__global__ void __launch_bounds__(256) fc_kernel(
    const float4* __restrict__ a, const float4* __restrict__ w,
    const float* __restrict__ fc_b, float* __restrict__ out)
{
    int tid = blockIdx.x * 256 + threadIdx.x;
    float s = 0.f;
    for (int i = tid; i < NN * 16; i += 512 * 256) {
        float4 xa = a[i], xw = w[i];
        s += xa.x * xw.x + xa.y * xw.y + xa.z * xw.z + xa.w * xw.w;
    }
    __shared__ float red[256];
    red[threadIdx.x] = s;
    __syncthreads();
    for (int st = 128; st > 0; st >>= 1) {
        if (threadIdx.x < st) red[threadIdx.x] += red[threadIdx.x + st];
        __syncthreads();
    }
    if (threadIdx.x == 0) {
        atomicAdd(&g_facc, red[0]);
        __threadfence();
        int c = atomicAdd(&g_fcnt, 1);
        if (c == 511) {
            float tot = atomicAdd(&g_facc, 0.f);
            out[0] = 1.f / (1.f + expf(-(tot + fc_b[0])));
        }
    }
}

// ---------------------------------------------------------------------------
extern "C" void kernel_launch(void* const* d_in, const int* in_sizes, int n_in,
                              void* d_out, int out_size)
{
    const float* features = (const float*)d_in[0];
    const float* V        = (const float*)d_in[1];
    const float* comp     = (const float*)d_in[2];
    const float* loop_w   = (const float*)d_in[3];
    const float* bias     = (const float*)d_in[4];
    const float* fc_w     = (const float*)d_in[5];
    const float* fc_b     = (const float*)d_in[6];
    const int*   src      = (const int*)d_in[7];
    const int*   dst      = (const int*)d_in[8];
    const int*   et       = (const int*)d_in[9];
    float* out = (float*)d_out;

    void *p_projh, *p_h1, *p_h2, *p_deg, *p_cur, *p_tflag, *p_csr, *p_wp;
    cudaGetSymbolAddress(&p_projh, g_projh);
    cudaGetSymbolAddress(&p_h1, g_h1a);
    cudaGetSymbolAddress(&p_h2, g_h2a);
    cudaGetSymbolAddress(&p_deg, g_deg);
    cudaGetSymbolAddress(&p_cur, g_cursor);
    cudaGetSymbolAddress(&p_tflag, g_tflag);
    cudaGetSymbolAddress(&p_csr, g_csr);
    cudaGetSymbolAddress(&p_wp, g_wpack);

    const int e4_blocks   = (NE / 4 + 255) / 256;
    const int e1_blocks   = (NE + 255) / 256;
    const int gemm_blocks = (NN + 63) / 64;
    const int agg_blocks  = ((NE / AGGQ) * 16 + 255) / 256;   // 6250

    cudaStream_t s2;
    cudaStreamCreateWithFlags(&s2, cudaStreamNonBlocking);
    cudaEvent_t eFork, eJoin, ePref;
    cudaEventCreateWithFlags(&eFork, cudaEventDisableTiming);
    cudaEventCreateWithFlags(&eJoin, cudaEventDisableTiming);
    cudaEventCreateWithFlags(&ePref, cudaEventDisableTiming);

    cudaEventRecord(eFork, 0);
    cudaStreamWaitEvent(s2, eFork, 0);

    // Enqueue order chosen so ncu's fixed slot (launch index 3) = gemm_tc.
    wprep_kernel<<<48, 256>>>(V, loop_w, (uint2*)p_wp);                    // 0
    hist_kernel<<<e4_blocks, 256, 0, s2>>>((const int4*)dst, (int*)p_deg); // 1
    scan_kernel<<<NTILES, 512, 0, s2>>>((int*)p_deg, (int*)p_cur,
                                        (int*)p_tflag);                    // 2
    gemm_tc<<<gemm_blocks, 256>>>(features, (const uint2*)p_wp, bias,
                                  (__half*)p_projh, (float*)p_h1, 0);      // 3
    scatter_kernel<<<e1_blocks, 256, 0, s2>>>(src, dst, et, (int*)p_cur,
                                              (int2*)p_csr, (int*)p_tflag);// 4
    cudaEventRecord(eJoin, s2);
    prefetch_kernel<<<256, 256, 0, s2>>>((const float4*)fc_w);             // 5
    cudaEventRecord(ePref, s2);

    cudaStreamWaitEvent(0, eJoin, 0);   // csr/cursor ready for agg0

    agg_kernel<<<agg_blocks, 256>>>((const uint4*)p_projh, (const int2*)p_csr,
                                    comp, (float4*)p_h1);                  // 6
    gemm_tc<<<gemm_blocks, 256>>>((const float*)p_h1,
                                  (const uint2*)p_wp + 6144, bias + 64,
                                  (__half*)p_projh, (float*)p_h2, 1);      // 7
    agg_kernel<<<agg_blocks, 256>>>((const uint4*)p_projh, (const int2*)p_csr,
                                    comp + 16, (float4*)p_h2);             // 8

    cudaStreamWaitEvent(0, ePref, 0);   // join side stream fully before fc
    fc_kernel<<<512, 256>>>((const float4*)p_h2, (const float4*)fc_w, fc_b,
                            out);                                          // 9

    cudaEventDestroy(eFork);
    cudaEventDestroy(eJoin);
    cudaEventDestroy(ePref);
    cudaStreamDestroy(s2);
}

// round 13
// speedup vs baseline: 1.1666x; 1.0573x over previous
#include <cuda_runtime.h>
#include <cuda_fp16.h>
#include <math.h>

#define NN 50000
#define NE 800000
#define NTILES 98      // ceil((NN+1)/512)
#define GSTRIDE 68     // A smem stride (conflict-free frag loads)
#define AGGQ 8         // edges per half-warp quota

// ---------------- scratch (static __device__, allocation-free) ----------------
__device__ uint4  g_projh[NN * 16];     // [N][16] x 16B: {b0 4h | b1 4h} per sub
__device__ float4 g_h1a[NN * 16];       // layer-1 hidden fp32
__device__ float4 g_h2a[NN * 16];       // layer-2 hidden fp32
__device__ int    g_deg[NN];            // self-clearing (scan zeroes after read)
__device__ int    g_cursor[NN];
__device__ int    g_tflag[128];         // cleared by scatter each run
__device__ int2   g_csr[NE];            // {src | etype<<17, dst}
__device__ uint2  g_wpack[2 * 24 * 8 * 32];   // frag-major tf32 weights
__device__ float  g_facc;
__device__ int    g_fcnt;
__device__ float  g_sink;

static __device__ __forceinline__ unsigned f2tf32(float f)
{
    unsigned u;
    asm("cvt.rna.tf32.f32 %0, %1;" : "=r"(u) : "f"(f));
    return u;
}

// ---------------- CSR build (side stream) ----------------
__global__ void __launch_bounds__(256) hist_kernel(const int4* __restrict__ dst4,
                                                   int* __restrict__ deg)
{
    int t = blockIdx.x * 256 + threadIdx.x;
    if (t >= NE / 4) return;
    int4 d = __ldg(dst4 + t);
    atomicAdd(&deg[d.x], 1);
    atomicAdd(&deg[d.y], 1);
    atomicAdd(&deg[d.z], 1);
    atomicAdd(&deg[d.w], 1);
}

// Warp-shuffle decoupled-lookback scan; self-clears deg for the next replay.
__global__ void __launch_bounds__(512) scan_kernel(
    int* __restrict__ deg, int* __restrict__ cursor, int* __restrict__ tflag)
{
    __shared__ int wsum[16];
    __shared__ int wpre[16];
    __shared__ int s_prefix;
    const int t = threadIdx.x;
    const int warp = t >> 5;
    const int lane = t & 31;
    const int tile = blockIdx.x;
    const int g = tile * 512 + t;

    int v = (g < NN) ? deg[g] : 0;
    int x = v;
#pragma unroll
    for (int d = 1; d < 32; d <<= 1) {
        int y = __shfl_up_sync(0xFFFFFFFFu, x, d);
        if (lane >= d) x += y;
    }
    if (lane == 31) wsum[warp] = x;
    if (t == 32) s_prefix = 0;
    __syncthreads();

    if (warp == 0 && lane < 16) {
        int s = wsum[lane];
        int p = s;
#pragma unroll
        for (int d = 1; d < 16; d <<= 1) {
            int y = __shfl_up_sync(0xFFFFu, p, d);
            if (lane >= d) p += y;
        }
        wpre[lane] = p - s;
        if (lane == 15) atomicExch(&tflag[tile], p + 1);
    }

    if (tile > 0 && warp == 1) {
        int sum = 0;
        for (int base = tile - 1; base >= 0; base -= 32) {
            int idx = base - lane;
            int val = 0;
            if (idx >= 0) {
                int f;
                do { f = atomicAdd(&tflag[idx], 0); } while (f == 0);
                val = f - 1;
            }
#pragma unroll
            for (int o = 16; o; o >>= 1) val += __shfl_xor_sync(0xFFFFFFFFu, val, o);
            sum += val;
        }
        if (lane == 0) s_prefix = sum;
    }
    __syncthreads();

    if (g < NN) {
        cursor[g] = s_prefix + wpre[warp] + x - v;
        deg[g] = 0;
    }
}

// 1 edge/thread; block 0 clears tflag (stream-ordered after scan).
__global__ void __launch_bounds__(256) scatter_kernel(
    const int* __restrict__ src, const int* __restrict__ dst,
    const int* __restrict__ et, int* __restrict__ cursor,
    int2* __restrict__ csr, int* __restrict__ tflag)
{
    if (blockIdx.x == 0 && threadIdx.x < 128) tflag[threadIdx.x] = 0;
    int e = blockIdx.x * 256 + threadIdx.x;
    if (e >= NE) return;
    int d = __ldg(dst + e);
    int pos = atomicAdd(&cursor[d], 1);
    csr[pos] = make_int2(__ldg(src + e) | (__ldg(et + e) << 17), d);
}

// L2 warmer for fc_w
__global__ void __launch_bounds__(256) prefetch_kernel(const float4* __restrict__ w)
{
    int tid = blockIdx.x * 256 + threadIdx.x;
    float s = 0.f;
    for (int i = tid; i < NN * 16; i += 256 * 256) {
        float4 v = __ldg(w + i);
        s += v.x + v.y + v.z + v.w;
    }
    if (s == 1.2345e37f) g_sink = s;
}

// ---------------------------------------------------------------------------
// Weight prep + FC accumulator reset
// ---------------------------------------------------------------------------
__global__ void __launch_bounds__(256) wprep_kernel(
    const float* __restrict__ V, const float* __restrict__ lw,
    uint2* __restrict__ wpack)
{
    int id = blockIdx.x * 256 + threadIdx.x;
    if (id == 0) { g_facc = 0.f; g_fcnt = 0; }
    if (id >= 2 * 24 * 8 * 32) return;
    int lay  = id / 6144;
    int r    = id - lay * 6144;
    int nt   = r >> 8;
    int s    = (r >> 5) & 7;
    int lane = r & 31;
    int o  = nt * 8 + (lane >> 2);
    int k0 = s * 8 + (lane & 3);
    float w0, w1;
    if (o < 128) {
        int b = o >> 6, c = o & 63;
        w0 = V[(((lay * 2 + b) * 64) + k0) * 64 + c];
        w1 = V[(((lay * 2 + b) * 64) + k0 + 4) * 64 + c];
    } else {
        w0 = lw[(lay * 64 + k0) * 64 + (o - 128)];
        w1 = lw[(lay * 64 + k0 + 4) * 64 + (o - 128)];
    }
    wpack[id] = make_uint2(f2tf32(w0), f2tf32(w1));
}

// ---------------------------------------------------------------------------
// Tensor-core node GEMM: [50000x64] @ [64x192] via mma.sync.m16n8k8.tf32.
// Epilogue staged through smem (reusing xs) for fully-coalesced STG.128.
// launch_bounds(256,3) -> 85-reg cap -> 3 CTAs/SM.
// ---------------------------------------------------------------------------
__global__ void __launch_bounds__(256, 3) gemm_tc(
    const float* __restrict__ x, const uint2* __restrict__ wpack,
    const float* __restrict__ bias, __half* __restrict__ projh,
    float* __restrict__ h, int relu_in)
{
    __shared__ unsigned xs[64 * GSTRIDE];     // 17408 B; reused as epilogue stage
    const int tid = threadIdx.x;
    const int nbase = blockIdx.x * 64;

    {
        int nl = tid >> 2;
        int c0 = (tid & 3) * 16;
        int n = nbase + nl;
        const float4* xr = (const float4*)(x + (size_t)n * 64 + c0);
#pragma unroll
        for (int u = 0; u < 4; ++u) {
            float4 v = (n < NN) ? __ldg(xr + u) : make_float4(0.f, 0.f, 0.f, 0.f);
            if (relu_in) {
                v.x = fmaxf(v.x, 0.f); v.y = fmaxf(v.y, 0.f);
                v.z = fmaxf(v.z, 0.f); v.w = fmaxf(v.w, 0.f);
            }
            unsigned* dstp = xs + nl * GSTRIDE + c0 + u * 4;
            dstp[0] = f2tf32(v.x); dstp[1] = f2tf32(v.y);
            dstp[2] = f2tf32(v.z); dstp[3] = f2tf32(v.w);
        }
    }
    __syncthreads();

    const int w    = tid >> 5;
    const int lane = tid & 31;
    const int m0   = (w & 3) << 4;
    const int ng   = w >> 2;
    const int g    = lane >> 2;
    const int t4   = lane & 3;

    float acc[12][4];
#pragma unroll
    for (int j = 0; j < 12; ++j)
#pragma unroll
        for (int c = 0; c < 4; ++c) acc[j][c] = 0.f;

    const uint2* wp = wpack + ((size_t)ng * 12 * 8 * 32) + lane;

#pragma unroll
    for (int s = 0; s < 8; ++s) {
        int k0 = s * 8;
        unsigned a0 = xs[(m0 + g) * GSTRIDE + k0 + t4];
        unsigned a1 = xs[(m0 + g + 8) * GSTRIDE + k0 + t4];
        unsigned a2 = xs[(m0 + g) * GSTRIDE + k0 + t4 + 4];
        unsigned a3 = xs[(m0 + g + 8) * GSTRIDE + k0 + t4 + 4];
        uint2 b[12];
#pragma unroll
        for (int j = 0; j < 12; ++j) b[j] = __ldg(wp + (j * 8 + s) * 32);
#pragma unroll
        for (int j = 0; j < 12; ++j)
            asm volatile(
                "mma.sync.aligned.m16n8k8.row.col.f32.tf32.tf32.f32 "
                "{%0,%1,%2,%3}, {%4,%5,%6,%7}, {%8,%9}, {%0,%1,%2,%3};"
                : "+f"(acc[j][0]), "+f"(acc[j][1]), "+f"(acc[j][2]), "+f"(acc[j][3])
                : "r"(a0), "r"(a1), "r"(a2), "r"(a3), "r"(b[j].x), "r"(b[j].y));
    }
    __syncthreads();    // all warps done reading xs; safe to reuse

    // ---- Phase 1: proj (fp16, interleaved layout) via smem, then coalesced ----
    {
        __half* sp = (__half*)xs;             // [64][132] halves = 16896 B
#pragma unroll
        for (int j = 0; j < 12; ++j) {
            int o = ng * 96 + j * 8 + t4 * 2;
            if (o < 128) {
                int basis = o >> 6, c64 = o & 63;
                int off = ((c64 >> 2) << 3) + (basis << 2) + (c64 & 3);
#pragma unroll
                for (int rr = 0; rr < 2; ++rr) {
                    int nl = m0 + g + rr * 8;
                    *(__half2*)(sp + nl * 132 + off) =
                        __floats2half2_rn(acc[j][rr * 2], acc[j][rr * 2 + 1]);
                }
            }
        }
        __syncthreads();
        const unsigned* sp32 = (const unsigned*)xs;
        for (int idx = tid; idx < 1024; idx += 256) {
            int nl = idx >> 4, sub = idx & 15;
            int n = nbase + nl;
            if (n < NN) {
                int wi = nl * 66 + sub * 4;
                uint4 v = make_uint4(sp32[wi], sp32[wi + 1], sp32[wi + 2], sp32[wi + 3]);
                ((uint4*)projh)[(size_t)n * 16 + sub] = v;
            }
        }
        __syncthreads();
    }

    // ---- Phase 2: h (fp32 + bias) via smem, then coalesced ----
    {
        float* hp = (float*)xs;               // [64][66] floats = 16896 B
        if (ng == 1) {
#pragma unroll
            for (int j = 4; j < 12; ++j) {
                int o = 96 + j * 8 + t4 * 2;  // >= 128
                int c = o - 128;
                float b0 = __ldg(bias + c), b1 = __ldg(bias + c + 1);
#pragma unroll
                for (int rr = 0; rr < 2; ++rr) {
                    int nl = m0 + g + rr * 8;
                    float2 f;
                    f.x = acc[j][rr * 2] + b0;
                    f.y = acc[j][rr * 2 + 1] + b1;
                    *(float2*)(hp + nl * 66 + c) = f;
                }
            }
        }
        __syncthreads();
        const float* hf = (const float*)xs;
        for (int idx = tid; idx < 1024; idx += 256) {
            int nl = idx >> 4, c4 = idx & 15;
            int n = nbase + nl;
            if (n < NN) {
                int wi = nl * 66 + c4 * 4;
                float4 v = make_float4(hf[wi], hf[wi + 1], hf[wi + 2], hf[wi + 3]);
                ((float4*)h)[(size_t)n * 16 + c4] = v;
            }
        }
    }
}

// ---------------------------------------------------------------------------
// Edge-balanced aggregation: half-warp per 8-edge CSR window.
// ---------------------------------------------------------------------------
__global__ void __launch_bounds__(256) agg_kernel(
    const uint4* __restrict__ proj, const int2* __restrict__ csr,
    const float* __restrict__ comp_l, float4* __restrict__ h)
{
    __shared__ float scomp[16];
    if (threadIdx.x < 16) scomp[threadIdx.x] = comp_l[threadIdx.x];
    __syncthreads();

    int gid = blockIdx.x * 256 + threadIdx.x;
    int q = gid >> 4;
    if (q >= NE / AGGQ) return;
    int sub = gid & 15;
    int j0 = q * AGGQ;
    unsigned hmask = 0xFFFFu << (threadIdx.x & 16);

    int2 rec = (sub < AGGQ) ? __ldg(csr + j0 + sub) : make_int2(0, 0);

    int pk[AGGQ], dk[AGGQ];
#pragma unroll
    for (int k = 0; k < AGGQ; ++k) {
        pk[k] = __shfl_sync(hmask, rec.x, k, 16);
        dk[k] = __shfl_sync(hmask, rec.y, k, 16);
    }

    uint4 a[AGGQ];
#pragma unroll
    for (int k = 0; k < AGGQ; ++k)
        a[k] = __ldg(proj + (size_t)(pk[k] & 0x1FFFF) * 16 + sub);

    float4 acc = make_float4(0.f, 0.f, 0.f, 0.f);
    int cur_d = dk[0];

#define FLUSH()                                                             \
    {                                                                       \
        float4* hp = h + (size_t)cur_d * 16 + sub;                          \
        asm volatile("red.global.add.v4.f32 [%0], {%1,%2,%3,%4};"           \
                     :: "l"(hp), "f"(acc.x), "f"(acc.y), "f"(acc.z),        \
                        "f"(acc.w) : "memory");                             \
    }

#pragma unroll
    for (int k = 0; k < AGGQ; ++k) {
        if (dk[k] != cur_d) {
            FLUSH();
            acc = make_float4(0.f, 0.f, 0.f, 0.f);
            cur_d = dk[k];
        }
        int tt = pk[k] >> 17;
        float c0 = scomp[2 * tt], c1 = scomp[2 * tt + 1];
        float2 f0a = __half22float2(*(__half2*)&a[k].x);
        float2 f0b = __half22float2(*(__half2*)&a[k].y);
        float2 f1a = __half22float2(*(__half2*)&a[k].z);
        float2 f1b = __half22float2(*(__half2*)&a[k].w);
        acc.x = fmaf(c0, f0a.x, fmaf(c1, f1a.x, acc.x));
        acc.y = fmaf(c0, f0a.y, fmaf(c1, f1a.y, acc.y));
        acc.z = fmaf(c0, f0b.x, fmaf(c1, f1b.x, acc.z));
        acc.w = fmaf(c0, f0b.y, fmaf(c1, f1b.y, acc.w));
    }
    FLUSH();
#undef FLUSH
}

// ---------------------------------------------------------------------------
// FC readout
// ---------------------------------------------------------------------------
__global__ void __launch_bounds__(256) fc_kernel(
    const float4* __restrict__ a, const float4* __restrict__ w,
    const float* __restrict__ fc_b, float* __restrict__ out)
{
    int tid = blockIdx.x * 256 + threadIdx.x;
    float s = 0.f;
    for (int i = tid; i < NN * 16; i += 512 * 256) {
        float4 xa = a[i], xw = w[i];
        s += xa.x * xw.x + xa.y * xw.y + xa.z * xw.z + xa.w * xw.w;
    }
    __shared__ float red[256];
    red[threadIdx.x] = s;
    __syncthreads();
    for (int st = 128; st > 0; st >>= 1) {
        if (threadIdx.x < st) red[threadIdx.x] += red[threadIdx.x + st];
        __syncthreads();
    }
    if (threadIdx.x == 0) {
        atomicAdd(&g_facc, red[0]);
        __threadfence();
        int c = atomicAdd(&g_fcnt, 1);
        if (c == 511) {
            float tot = atomicAdd(&g_facc, 0.f);
            out[0] = 1.f / (1.f + expf(-(tot + fc_b[0])));
        }
    }
}

// ---------------------------------------------------------------------------
extern "C" void kernel_launch(void* const* d_in, const int* in_sizes, int n_in,
                              void* d_out, int out_size)
{
    const float* features = (const float*)d_in[0];
    const float* V        = (const float*)d_in[1];
    const float* comp     = (const float*)d_in[2];
    const float* loop_w   = (const float*)d_in[3];
    const float* bias     = (const float*)d_in[4];
    const float* fc_w     = (const float*)d_in[5];
    const float* fc_b     = (const float*)d_in[6];
    const int*   src      = (const int*)d_in[7];
    const int*   dst      = (const int*)d_in[8];
    const int*   et       = (const int*)d_in[9];
    float* out = (float*)d_out;

    void *p_projh, *p_h1, *p_h2, *p_deg, *p_cur, *p_tflag, *p_csr, *p_wp;
    cudaGetSymbolAddress(&p_projh, g_projh);
    cudaGetSymbolAddress(&p_h1, g_h1a);
    cudaGetSymbolAddress(&p_h2, g_h2a);
    cudaGetSymbolAddress(&p_deg, g_deg);
    cudaGetSymbolAddress(&p_cur, g_cursor);
    cudaGetSymbolAddress(&p_tflag, g_tflag);
    cudaGetSymbolAddress(&p_csr, g_csr);
    cudaGetSymbolAddress(&p_wp, g_wpack);

    const int e4_blocks   = (NE / 4 + 255) / 256;
    const int e1_blocks   = (NE + 255) / 256;
    const int gemm_blocks = (NN + 63) / 64;
    const int agg_blocks  = ((NE / AGGQ) * 16 + 255) / 256;

    cudaStream_t s2;
    cudaStreamCreateWithFlags(&s2, cudaStreamNonBlocking);
    cudaEvent_t eFork, eJoin, ePref;
    cudaEventCreateWithFlags(&eFork, cudaEventDisableTiming);
    cudaEventCreateWithFlags(&eJoin, cudaEventDisableTiming);
    cudaEventCreateWithFlags(&ePref, cudaEventDisableTiming);

    cudaEventRecord(eFork, 0);
    cudaStreamWaitEvent(s2, eFork, 0);

    // Enqueue order keeps ncu's slot (launch index 3) on gemm_tc.
    wprep_kernel<<<48, 256>>>(V, loop_w, (uint2*)p_wp);                    // 0
    hist_kernel<<<e4_blocks, 256, 0, s2>>>((const int4*)dst, (int*)p_deg); // 1
    scan_kernel<<<NTILES, 512, 0, s2>>>((int*)p_deg, (int*)p_cur,
                                        (int*)p_tflag);                    // 2
    gemm_tc<<<gemm_blocks, 256>>>(features, (const uint2*)p_wp, bias,
                                  (__half*)p_projh, (float*)p_h1, 0);      // 3
    scatter_kernel<<<e1_blocks, 256, 0, s2>>>(src, dst, et, (int*)p_cur,
                                              (int2*)p_csr, (int*)p_tflag);// 4
    cudaEventRecord(eJoin, s2);
    prefetch_kernel<<<256, 256, 0, s2>>>((const float4*)fc_w);             // 5
    cudaEventRecord(ePref, s2);

    cudaStreamWaitEvent(0, eJoin, 0);

    agg_kernel<<<agg_blocks, 256>>>((const uint4*)p_projh, (const int2*)p_csr,
                                    comp, (float4*)p_h1);                  // 6
    gemm_tc<<<gemm_blocks, 256>>>((const float*)p_h1,
                                  (const uint2*)p_wp + 6144, bias + 64,
                                  (__half*)p_projh, (float*)p_h2, 1);      // 7
    agg_kernel<<<agg_blocks, 256>>>((const uint4*)p_projh, (const int2*)p_csr,
                                    comp + 16, (float4*)p_h2);             // 8

    cudaStreamWaitEvent(0, ePref, 0);
    fc_kernel<<<512, 256>>>((const float4*)p_h2, (const float4*)fc_w, fc_b,
                            out);                                          // 9

    cudaEventDestroy(eFork);
    cudaEventDestroy(eJoin);
    cudaEventDestroy(ePref);
    cudaStreamDestroy(s2);
}